// round 11
// baseline (speedup 1.0000x reference)
#include <cuda_runtime.h>
#include <math.h>

// Problem constants
constexpr int NB  = 8;
constexpr int NT  = 2048;
constexpr int ND  = 1024;
constexpr int NP  = 512;
constexpr int NS  = 256;
constexpr int NH  = 256;
constexpr int NBT = NB * NT;      // 16384
constexpr int NW  = 512;          // fused h|qk width

constexpr float TAUF = 1e-5f;     // at-risk flag window (fp32 pass error ~1e-6)

// ---------------- device scratch (static allocations only) ----------------
__device__ float g_hq[NBT * NW];         // [h | qk] fused output
__device__ float g_scores[NBT];
__device__ int   g_order[NBT];           // per-batch sorted token indices
__device__ float g_sscores[NBT];         // per-batch sorted scores
__device__ float g_sum[NB * NP * NS];    // summaries
__device__ float g_pool[NB * NP * NS];   // updated pool
__device__ float g_pri[NB * NP];
__device__ int   g_counts[NB];
__device__ float g_wkT[NS * NS];         // wk^T
__device__ float g_wqk[ND * NS];         // wq @ wk^T
__device__ float g_wcat[ND * NW];        // [w1 | wqk]
__device__ float g_poolT[NB * NS * NP];  // transposed pool
__device__ float g_ap[NBT * NS];         // attn @ pool
__device__ float g_attn[NB * NT * NP];   // attention weights
__device__ int   g_flagcnt;
__device__ int   g_flaglist[NBT];

// ------- 128x128x16 double-buffered SGEMM, 8x8 microtile (4+4 split) -------
// C = A(MxK, row stride lda) @ B(KxN), row-major.
__global__ __launch_bounds__(256, 2)
void sgemm128_kernel(const float* __restrict__ A, const float* __restrict__ Bm,
                     float* __restrict__ C, int M, int N, int K, int lda,
                     long long sA, long long sB, long long sC) {
    A  += (long long)blockIdx.z * sA;
    Bm += (long long)blockIdx.z * sB;
    C  += (long long)blockIdx.z * sC;
    __shared__ float As[2][16][128];   // k-major (transposed on store)
    __shared__ float Bs[2][16][128];

    const int tid  = threadIdx.x;
    const int row0 = blockIdx.y * 128, col0 = blockIdx.x * 128;
    const int ar = tid >> 1;              // 0..127
    const int ac = (tid & 1) << 3;        // 0 or 8
    const int br = tid >> 4;              // 0..15
    const int bc = (tid & 15) << 3;       // 0..120
    const float* Ap = A + (long long)(row0 + ar) * lda + ac;
    const float* Bp = Bm + (long long)br * N + col0 + bc;
    const int tx4 = (tid & 15) << 2;      // 0..60
    const int ty4 = (tid >> 4) << 2;      // 0..60

    float acc[8][8] = {};
    float af[2][8], bf[2][8];
    float4 av0 = *(const float4*)Ap;
    float4 av1 = *(const float4*)(Ap + 4);
    float4 bv0 = *(const float4*)Bp;
    float4 bv1 = *(const float4*)(Bp + 4);
    int buf = 0;
    As[0][ac + 0][ar] = av0.x; As[0][ac + 1][ar] = av0.y;
    As[0][ac + 2][ar] = av0.z; As[0][ac + 3][ar] = av0.w;
    As[0][ac + 4][ar] = av1.x; As[0][ac + 5][ar] = av1.y;
    As[0][ac + 6][ar] = av1.z; As[0][ac + 7][ar] = av1.w;
    *(float4*)&Bs[0][br][bc]     = bv0;
    *(float4*)&Bs[0][br][bc + 4] = bv1;
    __syncthreads();
    *(float4*)&af[0][0] = *(const float4*)&As[0][0][ty4];
    *(float4*)&af[0][4] = *(const float4*)&As[0][0][ty4 + 64];
    *(float4*)&bf[0][0] = *(const float4*)&Bs[0][0][tx4];
    *(float4*)&bf[0][4] = *(const float4*)&Bs[0][0][tx4 + 64];

    for (int k0 = 16; k0 <= K; k0 += 16) {
        if (k0 < K) {                       // prefetch next tile into regs
            av0 = *(const float4*)(Ap + k0);
            av1 = *(const float4*)(Ap + k0 + 4);
            bv0 = *(const float4*)(Bp + (long long)k0 * N);
            bv1 = *(const float4*)(Bp + (long long)k0 * N + 4);
        }
#pragma unroll
        for (int kk = 0; kk < 16; kk++) {
            const int cur = kk & 1;
            if (kk < 15) {                  // pipeline: load kk+1 fragments
                const int nxt = cur ^ 1;
                *(float4*)&af[nxt][0] = *(const float4*)&As[buf][kk + 1][ty4];
                *(float4*)&af[nxt][4] = *(const float4*)&As[buf][kk + 1][ty4 + 64];
                *(float4*)&bf[nxt][0] = *(const float4*)&Bs[buf][kk + 1][tx4];
                *(float4*)&bf[nxt][4] = *(const float4*)&Bs[buf][kk + 1][tx4 + 64];
            }
#pragma unroll
            for (int i = 0; i < 8; i++)
#pragma unroll
                for (int j = 0; j < 8; j++)
                    acc[i][j] = fmaf(af[cur][i], bf[cur][j], acc[i][j]);
        }
        if (k0 < K) {
            buf ^= 1;
            As[buf][ac + 0][ar] = av0.x; As[buf][ac + 1][ar] = av0.y;
            As[buf][ac + 2][ar] = av0.z; As[buf][ac + 3][ar] = av0.w;
            As[buf][ac + 4][ar] = av1.x; As[buf][ac + 5][ar] = av1.y;
            As[buf][ac + 6][ar] = av1.z; As[buf][ac + 7][ar] = av1.w;
            *(float4*)&Bs[buf][br][bc]     = bv0;
            *(float4*)&Bs[buf][br][bc + 4] = bv1;
            __syncthreads();
            *(float4*)&af[0][0] = *(const float4*)&As[buf][0][ty4];
            *(float4*)&af[0][4] = *(const float4*)&As[buf][0][ty4 + 64];
            *(float4*)&bf[0][0] = *(const float4*)&Bs[buf][0][tx4];
            *(float4*)&bf[0][4] = *(const float4*)&Bs[buf][0][tx4 + 64];
        }
    }
#pragma unroll
    for (int i = 0; i < 8; i++) {
        int r = row0 + ((i < 4) ? (ty4 + i) : (ty4 + 60 + i));  // +64+(i-4)
        float* crow = C + (long long)r * N + col0;
        *(float4*)(crow + tx4)      = make_float4(acc[i][0], acc[i][1], acc[i][2], acc[i][3]);
        *(float4*)(crow + tx4 + 64) = make_float4(acc[i][4], acc[i][5], acc[i][6], acc[i][7]);
    }
}

// ------- 64x128x16 variant (4x8 microtile) with optional row indirection ---
// If ord != nullptr: A row r maps to tokens row (b*NT + ord[b*NT + slot]),
// where b = r/NP, slot = r%NP (direct gather-free summaries GEMM).
__global__ __launch_bounds__(256, 2)
void sgemm64_kernel(const float* __restrict__ A, const float* __restrict__ Bm,
                    float* __restrict__ C, int M, int N, int K,
                    const int* __restrict__ ord) {
    __shared__ float As[2][16][64];    // k-major
    __shared__ float Bs[2][16][128];

    const int tid  = threadIdx.x;
    const int row0 = blockIdx.y * 64, col0 = blockIdx.x * 128;
    const int ar = tid >> 2;              // 0..63
    const int ac = (tid & 3) << 2;        // 0,4,8,12
    const int br = tid >> 4;              // 0..15
    const int bc = (tid & 15) << 3;       // 0..120
    long long arow = row0 + ar;
    if (ord) {
        int r = row0 + ar;
        int b = r >> 9;                   // /NP
        int slot = r & (NP - 1);
        arow = (long long)b * NT + ord[b * NT + slot];
    }
    const float* Ap = A + arow * K + ac;
    const float* Bp = Bm + (long long)br * N + col0 + bc;
    const int tx4 = (tid & 15) << 2;
    const int ty4 = (tid >> 4) << 2;

    float acc[4][8] = {};
    float af[2][4], bf[2][8];
    float4 av = *(const float4*)Ap;
    float4 bv0 = *(const float4*)Bp;
    float4 bv1 = *(const float4*)(Bp + 4);
    int buf = 0;
    As[0][ac + 0][ar] = av.x; As[0][ac + 1][ar] = av.y;
    As[0][ac + 2][ar] = av.z; As[0][ac + 3][ar] = av.w;
    *(float4*)&Bs[0][br][bc]     = bv0;
    *(float4*)&Bs[0][br][bc + 4] = bv1;
    __syncthreads();
    *(float4*)&af[0][0] = *(const float4*)&As[0][0][ty4];
    *(float4*)&bf[0][0] = *(const float4*)&Bs[0][0][tx4];
    *(float4*)&bf[0][4] = *(const float4*)&Bs[0][0][tx4 + 64];

    for (int k0 = 16; k0 <= K; k0 += 16) {
        if (k0 < K) {
            av  = *(const float4*)(Ap + k0);
            bv0 = *(const float4*)(Bp + (long long)k0 * N);
            bv1 = *(const float4*)(Bp + (long long)k0 * N + 4);
        }
#pragma unroll
        for (int kk = 0; kk < 16; kk++) {
            const int cur = kk & 1;
            if (kk < 15) {
                const int nxt = cur ^ 1;
                *(float4*)&af[nxt][0] = *(const float4*)&As[buf][kk + 1][ty4];
                *(float4*)&bf[nxt][0] = *(const float4*)&Bs[buf][kk + 1][tx4];
                *(float4*)&bf[nxt][4] = *(const float4*)&Bs[buf][kk + 1][tx4 + 64];
            }
#pragma unroll
            for (int i = 0; i < 4; i++)
#pragma unroll
                for (int j = 0; j < 8; j++)
                    acc[i][j] = fmaf(af[cur][i], bf[cur][j], acc[i][j]);
        }
        if (k0 < K) {
            buf ^= 1;
            As[buf][ac + 0][ar] = av.x; As[buf][ac + 1][ar] = av.y;
            As[buf][ac + 2][ar] = av.z; As[buf][ac + 3][ar] = av.w;
            *(float4*)&Bs[buf][br][bc]     = bv0;
            *(float4*)&Bs[buf][br][bc + 4] = bv1;
            __syncthreads();
            *(float4*)&af[0][0] = *(const float4*)&As[buf][0][ty4];
            *(float4*)&bf[0][0] = *(const float4*)&Bs[buf][0][tx4];
            *(float4*)&bf[0][4] = *(const float4*)&Bs[buf][0][tx4 + 64];
        }
    }
#pragma unroll
    for (int i = 0; i < 4; i++) {
        float* crow = C + (long long)(row0 + ty4 + i) * N + col0;
        *(float4*)(crow + tx4)      = make_float4(acc[i][0], acc[i][1], acc[i][2], acc[i][3]);
        *(float4*)(crow + tx4 + 64) = make_float4(acc[i][4], acc[i][5], acc[i][6], acc[i][7]);
    }
}

// ---------------- pack [w1 | wqk] -> wcat; also reset flag counter ---------
__global__ void pack_w_kernel(const float* __restrict__ w1) {
    int i = blockIdx.x * blockDim.x + threadIdx.x;   // over ND*NS
    int d = i >> 8, c = i & 255;
    g_wcat[d * NW + c]      = w1[i];
    g_wcat[d * NW + NS + c] = g_wqk[i];
    if (i == 0) g_flagcnt = 0;
}

// ---------------- scores: sigmoid(relu(hq[:, :256]) . w2) ------------------
__global__ void score_kernel(const float* __restrict__ w2) {
    int gw = (blockIdx.x * blockDim.x + threadIdx.x) >> 5;
    int lane = threadIdx.x & 31;
    if (gw >= NBT) return;
    const float* hr = g_hq + (long long)gw * NW;
    float s = 0.f;
#pragma unroll
    for (int j = 0; j < NH / 32; j++) {
        int c = lane + (j << 5);
        float v = hr[c];
        v = fmaxf(v, 0.f);
        s = fmaf(v, w2[c], s);
    }
#pragma unroll
    for (int o = 16; o; o >>= 1) s += __shfl_xor_sync(0xffffffffu, s, o);
    if (lane == 0) g_scores[gw] = 1.0f / (1.0f + expf(-s));
}

// ---------------- per-batch bitonic sort, descending score / ascending idx --
__global__ void sort_kernel() {
    __shared__ float sk[NT];
    __shared__ int   si[NT];
    int b = blockIdx.x, t = threadIdx.x;   // 1024 threads
    sk[t]        = g_scores[b * NT + t];        si[t]        = t;
    sk[t + 1024] = g_scores[b * NT + t + 1024]; si[t + 1024] = t + 1024;
    __syncthreads();
    for (int kk = 2; kk <= NT; kk <<= 1) {
        for (int j = kk >> 1; j > 0; j >>= 1) {
            for (int i = t; i < NT; i += 1024) {
                int ixj = i ^ j;
                if (ixj > i) {
                    bool ord = ((i & kk) == 0);
                    float s1 = sk[i], s2 = sk[ixj];
                    int   i1 = si[i], i2 = si[ixj];
                    bool pre = (s2 > s1) || (s2 == s1 && i2 < i1);
                    if (pre == ord) { sk[i] = s2; sk[ixj] = s1; si[i] = i2; si[ixj] = i1; }
                }
            }
            __syncthreads();
        }
    }
    g_order[b * NT + t]          = si[t];
    g_order[b * NT + t + 1024]   = si[t + 1024];
    g_sscores[b * NT + t]        = sk[t];
    g_sscores[b * NT + t + 1024] = sk[t + 1024];
}

// ---- fused at-risk flagging + compaction (per sorted position) ------------
__global__ void flag_compact_kernel(const float* __restrict__ pri_in) {
    __shared__ float pr[NP];
    int b = blockIdx.y;
    for (int i = threadIdx.x; i < NP; i += blockDim.x) pr[i] = pri_in[b * NP + i];
    __syncthreads();
    int p = blockIdx.x * blockDim.x + threadIdx.x;   // sorted position
    int gi = b * NT + p;
    float s = g_sscores[gi];
    bool f = fabsf(s - 0.5f) < TAUF;
    if (p > 0)      f |= fabsf(s - g_sscores[gi - 1]) < TAUF;
    if (p < NT - 1) f |= fabsf(s - g_sscores[gi + 1]) < TAUF;
#pragma unroll 8
    for (int i = 0; i < NP; i++) f |= fabsf(s - pr[i]) < TAUF;
    if (f) {
        int pos = atomicAdd(&g_flagcnt, 1);
        g_flaglist[pos] = b * NT + g_order[gi];
    }
}

// ---- double-float helpers (compensated fp32; error ~ n*eps^2 ~ 6e-14) ----
__device__ __forceinline__ void twoProd(float a, float b, float& p, float& e) {
    p = a * b;
    e = fmaf(a, b, -p);
}
__device__ __forceinline__ void twoSum(float a, float b, float& s, float& e) {
    s = a + b;
    float bb = s - a;
    e = (a - (s - bb)) + (b - bb);
}

// high-precision recompute of flagged tokens' scores on the fp32 pipe
__global__ void recompute_kernel(const float* __restrict__ tokens,
                                 const float* __restrict__ w1,
                                 const float* __restrict__ w2) {
    __shared__ double red[256];
    int j = threadIdx.x;   // 256 threads = H columns
    int n = g_flagcnt;
    if (blockIdx.x >= n) return;
    for (int li = blockIdx.x; li < n; li += gridDim.x) {
        int g = g_flaglist[li];
        const float* x = tokens + (long long)g * ND;
        const float* wcol = w1 + j;
        float hi = 0.f, lo = 0.f;
        for (int d = 0; d < ND; d++) {
            float p, pe, t;
            twoProd(x[d], wcol[(long long)d * NH], p, pe);
            twoSum(hi, p, hi, t);
            lo += t + pe;
        }
        double hd = (double)hi + (double)lo;
        float hf = fmaxf((float)hd, 0.0f);        // round to fp32, relu
        red[j] = (double)hf * (double)w2[j];
        __syncthreads();
        for (int s = 128; s; s >>= 1) {
            if (j < s) red[j] += red[j + s];
            __syncthreads();
        }
        if (j == 0) {
            double z = red[0];
            g_scores[g] = (float)(1.0 / (1.0 + exp(-z)));
        }
        __syncthreads();
    }
}

// ---------------- wide pool copy (input pool -> working pool) --------------
__global__ void copy_pool_kernel(const float* __restrict__ pool_in) {
    int i = blockIdx.x * blockDim.x + threadIdx.x;   // float4 index
    ((float4*)g_pool)[i] = ((const float4*)pool_in)[i];
}

// ---- sequential pool update, deferred-write design ------------------------
__global__ void update_kernel(const float* __restrict__ pri_in,
                              const int* __restrict__ counts_in) {
    int b = blockIdx.x, t = threadIdx.x;   // 256 threads
    int lane = t & 31, wid = t >> 5;
    __shared__ float pri[NP];
    __shared__ float ssl[NP];
    __shared__ int   lastw[NP];
    __shared__ float gmin[16];
    __shared__ int   gidx[16];
    __shared__ int   sh_cnt;
    pri[t]         = pri_in[b * NP + t];
    pri[t + 256]   = pri_in[b * NP + t + 256];
    ssl[t]         = g_sscores[b * NT + t];
    ssl[t + 256]   = g_sscores[b * NT + t + 256];
    lastw[t]       = -1;
    lastw[t + 256] = -1;
    __syncthreads();

    if (wid == 0) {
        for (int g = 0; g < 16; g++) {
            float v = pri[(g << 5) + lane];
            int  ix = (g << 5) + lane;
#pragma unroll
            for (int o = 16; o; o >>= 1) {
                float ov = __shfl_xor_sync(0xffffffffu, v, o);
                int   oi = __shfl_xor_sync(0xffffffffu, ix, o);
                if (ov < v || (ov == v && oi < ix)) { v = ov; ix = oi; }
            }
            if (lane == 0) { gmin[g] = v; gidx[g] = ix; }
        }
        __syncwarp();
        int cnt = counts_in[b];
        for (int slot = 0; slot < NP; slot++) {
            float sc = ssl[slot];
            if (!(sc > 0.5f)) break;           // sorted descending -> done
            if (cnt < NP) {                    // insert phase
                int ins = cnt++;
                if (lane == 0) { pri[ins] = sc; lastw[ins] = slot; }
                __syncwarp();
                int g = ins >> 5;              // rescan modified group
                float v = pri[(g << 5) + lane];
                int  ix = (g << 5) + lane;
#pragma unroll
                for (int o = 16; o; o >>= 1) {
                    float ov = __shfl_xor_sync(0xffffffffu, v, o);
                    int   oi = __shfl_xor_sync(0xffffffffu, ix, o);
                    if (ov < v || (ov == v && oi < ix)) { v = ov; ix = oi; }
                }
                if (lane == 0) { gmin[g] = v; gidx[g] = ix; }
                __syncwarp();
            }
            if (cnt >= NP) {                   // replace-min (post-insert state)
                float v = (lane < 16) ? gmin[lane] : 3.4e38f;
                int  ix = (lane < 16) ? gidx[lane] : 0x7fffffff;
#pragma unroll
                for (int o = 8; o; o >>= 1) {
                    float ov = __shfl_xor_sync(0xffffffffu, v, o);
                    int   oi = __shfl_xor_sync(0xffffffffu, ix, o);
                    if (ov < v || (ov == v && oi < ix)) { v = ov; ix = oi; }
                }
                v  = __shfl_sync(0xffffffffu, v, 0);
                ix = __shfl_sync(0xffffffffu, ix, 0);
                if (sc > v) {
                    if (lane == 0) { pri[ix] = sc; lastw[ix] = slot; }
                    __syncwarp();
                    int g = ix >> 5;           // rescan modified group
                    float vv = pri[(g << 5) + lane];
                    int   ii = (g << 5) + lane;
#pragma unroll
                    for (int o = 16; o; o >>= 1) {
                        float ov = __shfl_xor_sync(0xffffffffu, vv, o);
                        int   oi = __shfl_xor_sync(0xffffffffu, ii, o);
                        if (ov < vv || (ov == vv && oi < ii)) { vv = ov; ii = oi; }
                    }
                    if (lane == 0) { gmin[g] = vv; gidx[g] = ii; }
                    __syncwarp();
                }
            }
        }
        if (lane == 0) sh_cnt = cnt;
    }
    __syncthreads();

    g_pri[b * NP + t]       = pri[t];
    g_pri[b * NP + t + 256] = pri[t + 256];
    if (t == 0) g_counts[b] = sh_cnt;

    // parallel copy phase: one warp per destination row (last writer wins)
    float*       poolb = g_pool + (long long)b * NP * NS;
    const float* summb = g_sum + (long long)b * NP * NS;
    for (int d = wid; d < NP; d += 8) {
        int s = lastw[d];
        if (s >= 0) {
            const float4* srcr = (const float4*)(summb + (long long)s * NS);
            float4*       dstr = (float4*)(poolb + (long long)d * NS);
            dstr[lane]      = srcr[lane];
            dstr[lane + 32] = srcr[lane + 32];
        }
    }
}

// ---------------- generic batched transpose: src[R,C] -> dst[C,R] ----------
__global__ void transpose_kernel(const float* __restrict__ src, float* __restrict__ dst,
                                 int R, int C, long long sS, long long sD) {
    __shared__ float tile[32][33];
    src += (long long)blockIdx.z * sS;
    dst += (long long)blockIdx.z * sD;
    int r0 = blockIdx.x * 32, c0 = blockIdx.y * 32;
    int x = threadIdx.x, y = threadIdx.y;   // 32 x 8
#pragma unroll
    for (int i = 0; i < 32; i += 8)
        tile[y + i][x] = src[(long long)(r0 + y + i) * C + c0 + x];
    __syncthreads();
#pragma unroll
    for (int i = 0; i < 32; i += 8)
        dst[(long long)(c0 + y + i) * R + r0 + x] = tile[x][y + i];
}

// ---------------- masked softmax over attn rows (warp per row) -------------
__global__ void softmax_kernel() {
    int gw = (blockIdx.x * blockDim.x + threadIdx.x) >> 5;
    int lane = threadIdx.x & 31;
    if (gw >= NBT) return;
    int b = gw >> 11;
    int cnt = g_counts[b];
    float* row = g_attn + (long long)gw * NP;
    float vals[NP / 32];
    float m = -1e30f;
#pragma unroll
    for (int j = 0; j < NP / 32; j++) {
        int p = lane + (j << 5);
        float v = row[p] * 0.0625f;   // 1/sqrt(256)
        vals[j] = v;
        if (p < cnt) m = fmaxf(m, v);
    }
#pragma unroll
    for (int o = 16; o; o >>= 1) m = fmaxf(m, __shfl_xor_sync(0xffffffffu, m, o));
    float s = 0.f;
#pragma unroll
    for (int j = 0; j < NP / 32; j++) {
        int p = lane + (j << 5);
        float e = (p < cnt) ? expf(vals[j] - m) : 0.f;
        vals[j] = e;
        s += e;
    }
#pragma unroll
    for (int o = 16; o; o >>= 1) s += __shfl_xor_sync(0xffffffffu, s, o);
    float inv = (cnt > 0) ? 1.f / s : 0.f;
#pragma unroll
    for (int j = 0; j < NP / 32; j++) row[lane + (j << 5)] = vals[j] * inv;
}

// ---------------- export pool / priorities / counts into d_out -------------
__global__ void export_kernel(float* __restrict__ dst) {
    int i = blockIdx.x * blockDim.x + threadIdx.x;
    constexpr int PS = NB * NP * NS;
    if (i < PS) dst[i] = g_pool[i];
    else if (i < PS + NB * NP) dst[i] = g_pri[i - PS];
    else if (i < PS + NB * NP + NB) dst[i] = (float)g_counts[i - PS - NB * NP];
}

// ---------------- launch ----------------
extern "C" void kernel_launch(void* const* d_in, const int* in_sizes, int n_in,
                              void* d_out, int out_size) {
    const float* tokens = (const float*)d_in[0];
    const float* pool   = (const float*)d_in[1];
    const float* pri    = (const float*)d_in[2];
    const int*   counts = (const int*)d_in[3];
    const float* w1     = (const float*)d_in[4];
    const float* w2     = (const float*)d_in[5];
    const float* w_sum  = (const float*)d_in[6];
    const float* wq     = (const float*)d_in[7];
    const float* wk     = (const float*)d_in[8];
    const float* wv     = (const float*)d_in[9];
    float* out = (float*)d_out;
    (void)in_sizes; (void)n_in;

    float *phq, *psum, *ppool, *pwkT, *pwqk, *pwcat, *ppoolT, *pap, *pattn;
    int* pord;
    cudaGetSymbolAddress((void**)&phq,    g_hq);
    cudaGetSymbolAddress((void**)&psum,   g_sum);
    cudaGetSymbolAddress((void**)&ppool,  g_pool);
    cudaGetSymbolAddress((void**)&pwkT,   g_wkT);
    cudaGetSymbolAddress((void**)&pwqk,   g_wqk);
    cudaGetSymbolAddress((void**)&pwcat,  g_wcat);
    cudaGetSymbolAddress((void**)&ppoolT, g_poolT);
    cudaGetSymbolAddress((void**)&pap,    g_ap);
    cudaGetSymbolAddress((void**)&pattn,  g_attn);
    cudaGetSymbolAddress((void**)&pord,   g_order);

    // side stream: early pool copy + export tail
    cudaStream_t s1;
    cudaStreamCreateWithFlags(&s1, cudaStreamNonBlocking);
    cudaEvent_t evFork, evCP, evUPD, evEXP;
    cudaEventCreateWithFlags(&evFork, cudaEventDisableTiming);
    cudaEventCreateWithFlags(&evCP, cudaEventDisableTiming);
    cudaEventCreateWithFlags(&evUPD, cudaEventDisableTiming);
    cudaEventCreateWithFlags(&evEXP, cudaEventDisableTiming);

    cudaEventRecord(evFork, 0);
    cudaStreamWaitEvent(s1, evFork, 0);
    copy_pool_kernel<<<(NB * NP * NS / 4) / 256, 256, 0, s1>>>(pool);
    cudaEventRecord(evCP, s1);

    // main: wkT -> wqk -> pack -> fused h|qk GEMM
    transpose_kernel<<<dim3(NS / 32, NS / 32, 1), dim3(32, 8)>>>(wk, pwkT, NS, NS, 0, 0);
    sgemm128_kernel<<<dim3(NS / 128, ND / 128, 1), 256>>>(wq, pwkT, pwqk, ND, NS, NS, NS, 0, 0, 0);
    pack_w_kernel<<<(ND * NS) / 256, 256>>>(w1);
    sgemm128_kernel<<<dim3(NW / 128, NBT / 128, 1), 256>>>(tokens, pwcat, phq, NBT, NW, ND, ND, 0, 0, 0);
    // score path
    score_kernel<<<NBT / 8, 256>>>(w2);
    sort_kernel<<<NB, 1024>>>();
    flag_compact_kernel<<<dim3(NT / 256, NB), 256>>>(pri);
    recompute_kernel<<<512, 256>>>(tokens, w1, w2);
    sort_kernel<<<NB, 1024>>>();
    // summaries = tokens[order[0:512]] @ w_sum (gather-free, 64-row tiles)
    sgemm64_kernel<<<dim3(NS / 128, NB * NP / 64, 1), 256>>>(tokens, w_sum, psum, NB * NP, NS, ND, pord);
    // sequential per-batch update (needs pool copy done)
    cudaStreamWaitEvent(0, evCP, 0);
    update_kernel<<<NB, 256>>>(pri, counts);
    cudaEventRecord(evUPD, 0);
    // export on side stream (depends only on pool/pri/counts)
    constexpr int RET = NBT * ND;
    constexpr int REST = NB * NP * NS + NB * NP + NB;
    if (out_size >= RET + REST) {
        cudaStreamWaitEvent(s1, evUPD, 0);
        export_kernel<<<(REST + 255) / 256, 256, 0, s1>>>(out + (long long)RET);
    }
    // poolT = pool^T per batch
    transpose_kernel<<<dim3(NP / 32, NS / 32, NB), dim3(32, 8)>>>(ppool, ppoolT, NP, NS,
        (long long)NP * NS, (long long)NS * NP);
    // attn = qk @ poolT (qk = hq[:, 256:512], lda = NW)
    sgemm128_kernel<<<dim3(NP / 128, NT / 128, NB), 256>>>(phq + NS, ppoolT, pattn, NT, NP, NS, NW,
        (long long)NT * NW, (long long)NS * NP, (long long)NT * NP);
    softmax_kernel<<<NBT / 8, 256>>>();
    // ap = attn @ pool ; retrieved = ap @ wv
    sgemm128_kernel<<<dim3(NS / 128, NT / 128, NB), 256>>>(pattn, ppool, pap, NT, NS, NP, NP,
        (long long)NT * NP, (long long)NP * NS, (long long)NT * NS);
    sgemm128_kernel<<<dim3(ND / 128, NBT / 128, 1), 256>>>(pap, wv, out, NBT, ND, NS, NS, 0, 0, 0);
    // join export before returning control
    cudaEventRecord(evEXP, s1);
    cudaStreamWaitEvent(0, evEXP, 0);
}

// round 15
// speedup vs baseline: 1.1727x; 1.1727x over previous
#include <cuda_runtime.h>
#include <math.h>
#include <stdint.h>

// Problem constants
constexpr int NB  = 8;
constexpr int NT  = 2048;
constexpr int ND  = 1024;
constexpr int NP  = 512;
constexpr int NS  = 256;
constexpr int NH  = 256;
constexpr int NBT = NB * NT;      // 16384

constexpr float TAUF = 1e-5f;     // at-risk flag window (fp32 pass error ~1e-6)

// ---------------- device scratch (static allocations only) ----------------
__device__ float g_h[NBT * NH];          // tokens@w1 (pre-relu)
__device__ float g_q[NBT * NS];          // qk = tokens@(wq@wk^T)
__device__ float g_scores[NBT];
__device__ int   g_order[NBT];
__device__ float g_sscores[NBT];
__device__ float g_sum[NB * NP * NS];    // summaries
__device__ float g_pool[NB * NP * NS];   // updated pool
__device__ float g_pri[NB * NP];
__device__ int   g_counts[NB];
__device__ float g_wkT[NS * NS];
__device__ float g_wqk[ND * NS];
__device__ float g_poolT[NB * NS * NP];
__device__ float g_ap[NBT * NS];
__device__ float g_attn[NB * NT * NP];
__device__ int   g_flagcnt;
__device__ int   g_flaglist[NBT];

// ------- 128x128x16 double-buffered fp32 SGEMM (8x8 microtile) -------------
__global__ __launch_bounds__(256, 2)
void sgemm128_kernel(const float* __restrict__ A, const float* __restrict__ Bm,
                     float* __restrict__ C, int M, int N, int K, int lda,
                     long long sA, long long sB, long long sC) {
    A  += (long long)blockIdx.z * sA;
    Bm += (long long)blockIdx.z * sB;
    C  += (long long)blockIdx.z * sC;
    __shared__ float As[2][16][128];
    __shared__ float Bs[2][16][128];
    const int tid  = threadIdx.x;
    const int row0 = blockIdx.y * 128, col0 = blockIdx.x * 128;
    const int ar = tid >> 1, ac = (tid & 1) << 3;
    const int br = tid >> 4, bc = (tid & 15) << 3;
    const float* Ap = A + (long long)(row0 + ar) * lda + ac;
    const float* Bp = Bm + (long long)br * N + col0 + bc;
    const int tx4 = (tid & 15) << 2, ty4 = (tid >> 4) << 2;

    float acc[8][8] = {};
    float af[2][8], bf[2][8];
    float4 av0 = *(const float4*)Ap;
    float4 av1 = *(const float4*)(Ap + 4);
    float4 bv0 = *(const float4*)Bp;
    float4 bv1 = *(const float4*)(Bp + 4);
    int buf = 0;
    As[0][ac + 0][ar] = av0.x; As[0][ac + 1][ar] = av0.y;
    As[0][ac + 2][ar] = av0.z; As[0][ac + 3][ar] = av0.w;
    As[0][ac + 4][ar] = av1.x; As[0][ac + 5][ar] = av1.y;
    As[0][ac + 6][ar] = av1.z; As[0][ac + 7][ar] = av1.w;
    *(float4*)&Bs[0][br][bc]     = bv0;
    *(float4*)&Bs[0][br][bc + 4] = bv1;
    __syncthreads();
    *(float4*)&af[0][0] = *(const float4*)&As[0][0][ty4];
    *(float4*)&af[0][4] = *(const float4*)&As[0][0][ty4 + 64];
    *(float4*)&bf[0][0] = *(const float4*)&Bs[0][0][tx4];
    *(float4*)&bf[0][4] = *(const float4*)&Bs[0][0][tx4 + 64];

    for (int k0 = 16; k0 <= K; k0 += 16) {
        if (k0 < K) {
            av0 = *(const float4*)(Ap + k0);
            av1 = *(const float4*)(Ap + k0 + 4);
            bv0 = *(const float4*)(Bp + (long long)k0 * N);
            bv1 = *(const float4*)(Bp + (long long)k0 * N + 4);
        }
#pragma unroll
        for (int kk = 0; kk < 16; kk++) {
            const int cur = kk & 1;
            if (kk < 15) {
                const int nxt = cur ^ 1;
                *(float4*)&af[nxt][0] = *(const float4*)&As[buf][kk + 1][ty4];
                *(float4*)&af[nxt][4] = *(const float4*)&As[buf][kk + 1][ty4 + 64];
                *(float4*)&bf[nxt][0] = *(const float4*)&Bs[buf][kk + 1][tx4];
                *(float4*)&bf[nxt][4] = *(const float4*)&Bs[buf][kk + 1][tx4 + 64];
            }
#pragma unroll
            for (int i = 0; i < 8; i++)
#pragma unroll
                for (int j = 0; j < 8; j++)
                    acc[i][j] = fmaf(af[cur][i], bf[cur][j], acc[i][j]);
        }
        if (k0 < K) {
            buf ^= 1;
            As[buf][ac + 0][ar] = av0.x; As[buf][ac + 1][ar] = av0.y;
            As[buf][ac + 2][ar] = av0.z; As[buf][ac + 3][ar] = av0.w;
            As[buf][ac + 4][ar] = av1.x; As[buf][ac + 5][ar] = av1.y;
            As[buf][ac + 6][ar] = av1.z; As[buf][ac + 7][ar] = av1.w;
            *(float4*)&Bs[buf][br][bc]     = bv0;
            *(float4*)&Bs[buf][br][bc + 4] = bv1;
            __syncthreads();
            *(float4*)&af[0][0] = *(const float4*)&As[buf][0][ty4];
            *(float4*)&af[0][4] = *(const float4*)&As[buf][0][ty4 + 64];
            *(float4*)&bf[0][0] = *(const float4*)&Bs[buf][0][tx4];
            *(float4*)&bf[0][4] = *(const float4*)&Bs[buf][0][tx4 + 64];
        }
    }
#pragma unroll
    for (int i = 0; i < 8; i++) {
        int r = row0 + ((i < 4) ? (ty4 + i) : (ty4 + 60 + i));
        float* crow = C + (long long)r * N + col0;
        *(float4*)(crow + tx4)      = make_float4(acc[i][0], acc[i][1], acc[i][2], acc[i][3]);
        *(float4*)(crow + tx4 + 64) = make_float4(acc[i][4], acc[i][5], acc[i][6], acc[i][7]);
    }
}

// ---------------- tf32 tensor-core GEMM, 128x128x16 -----------------------
// 8 warps as 4x2; warp tile 32x64 = 2x8 m16n8k8 mma tiles. fp32 accumulate.
// cvt.rna.tf32.f32 destination must be .b32 -> return bits as uint32_t.
__device__ __forceinline__ uint32_t to_tf32(float x) {
    uint32_t r;
    asm("cvt.rna.tf32.f32 %0, %1;" : "=r"(r) : "f"(x));
    return r;
}

__global__ __launch_bounds__(256, 2)
void tgemm128_kernel(const float* __restrict__ A, const float* __restrict__ Bm,
                     float* __restrict__ C, int M, int N, int K, int lda,
                     long long sA, long long sB, long long sC) {
    A  += (long long)blockIdx.z * sA;
    Bm += (long long)blockIdx.z * sB;
    C  += (long long)blockIdx.z * sC;
    constexpr int LD = 136;            // pad -> conflict-free fragment loads
    __shared__ uint32_t As[2][16][LD]; // [k][row], tf32 bit patterns
    __shared__ uint32_t Bs[2][16][LD]; // [k][col]
    const int tid  = threadIdx.x;
    const int row0 = blockIdx.y * 128, col0 = blockIdx.x * 128;
    const int ar = tid >> 1, ac = (tid & 1) << 3;
    const int br = tid >> 4, bc = (tid & 15) << 3;
    const float* Ap = A + (long long)(row0 + ar) * lda + ac;
    const float* Bp = Bm + (long long)br * N + col0 + bc;
    const int wid = tid >> 5, lane = tid & 31;
    const int g = lane >> 2, tig = lane & 3;
    const int wr = (wid & 3) << 5;     // warp row 0..96
    const int wc = (wid >> 2) << 6;    // warp col 0/64

    float acc[2][8][4];
#pragma unroll
    for (int m = 0; m < 2; m++)
#pragma unroll
        for (int n = 0; n < 8; n++)
#pragma unroll
            for (int v = 0; v < 4; v++) acc[m][n][v] = 0.f;

    float4 av0 = *(const float4*)Ap;
    float4 av1 = *(const float4*)(Ap + 4);
    float4 bv0 = *(const float4*)Bp;
    float4 bv1 = *(const float4*)(Bp + 4);
    int buf = 0;
    As[0][ac + 0][ar] = to_tf32(av0.x); As[0][ac + 1][ar] = to_tf32(av0.y);
    As[0][ac + 2][ar] = to_tf32(av0.z); As[0][ac + 3][ar] = to_tf32(av0.w);
    As[0][ac + 4][ar] = to_tf32(av1.x); As[0][ac + 5][ar] = to_tf32(av1.y);
    As[0][ac + 6][ar] = to_tf32(av1.z); As[0][ac + 7][ar] = to_tf32(av1.w);
    Bs[0][br][bc + 0] = to_tf32(bv0.x); Bs[0][br][bc + 1] = to_tf32(bv0.y);
    Bs[0][br][bc + 2] = to_tf32(bv0.z); Bs[0][br][bc + 3] = to_tf32(bv0.w);
    Bs[0][br][bc + 4] = to_tf32(bv1.x); Bs[0][br][bc + 5] = to_tf32(bv1.y);
    Bs[0][br][bc + 6] = to_tf32(bv1.z); Bs[0][br][bc + 7] = to_tf32(bv1.w);
    __syncthreads();

    for (int k0 = 16; k0 <= K; k0 += 16) {
        if (k0 < K) {
            av0 = *(const float4*)(Ap + k0);
            av1 = *(const float4*)(Ap + k0 + 4);
            bv0 = *(const float4*)(Bp + (long long)k0 * N);
            bv1 = *(const float4*)(Bp + (long long)k0 * N + 4);
        }
#pragma unroll
        for (int ks = 0; ks < 16; ks += 8) {
            uint32_t a[2][4], b[8][2];
            const uint32_t* ra0 = As[buf][ks + tig];
            const uint32_t* ra1 = As[buf][ks + tig + 4];
#pragma unroll
            for (int m = 0; m < 2; m++) {
                int rb = wr + (m << 4) + g;
                a[m][0] = ra0[rb];
                a[m][1] = ra0[rb + 8];
                a[m][2] = ra1[rb];
                a[m][3] = ra1[rb + 8];
            }
            const uint32_t* rb0 = Bs[buf][ks + tig];
            const uint32_t* rb1 = Bs[buf][ks + tig + 4];
#pragma unroll
            for (int n = 0; n < 8; n++) {
                int cb = wc + (n << 3) + g;
                b[n][0] = rb0[cb];
                b[n][1] = rb1[cb];
            }
#pragma unroll
            for (int m = 0; m < 2; m++)
#pragma unroll
                for (int n = 0; n < 8; n++)
                    asm volatile(
                        "mma.sync.aligned.m16n8k8.row.col.f32.tf32.tf32.f32 "
                        "{%0,%1,%2,%3}, {%4,%5,%6,%7}, {%8,%9}, {%0,%1,%2,%3};"
                        : "+f"(acc[m][n][0]), "+f"(acc[m][n][1]),
                          "+f"(acc[m][n][2]), "+f"(acc[m][n][3])
                        : "r"(a[m][0]), "r"(a[m][1]), "r"(a[m][2]), "r"(a[m][3]),
                          "r"(b[n][0]), "r"(b[n][1]));
        }
        if (k0 < K) {
            buf ^= 1;
            As[buf][ac + 0][ar] = to_tf32(av0.x); As[buf][ac + 1][ar] = to_tf32(av0.y);
            As[buf][ac + 2][ar] = to_tf32(av0.z); As[buf][ac + 3][ar] = to_tf32(av0.w);
            As[buf][ac + 4][ar] = to_tf32(av1.x); As[buf][ac + 5][ar] = to_tf32(av1.y);
            As[buf][ac + 6][ar] = to_tf32(av1.z); As[buf][ac + 7][ar] = to_tf32(av1.w);
            Bs[buf][br][bc + 0] = to_tf32(bv0.x); Bs[buf][br][bc + 1] = to_tf32(bv0.y);
            Bs[buf][br][bc + 2] = to_tf32(bv0.z); Bs[buf][br][bc + 3] = to_tf32(bv0.w);
            Bs[buf][br][bc + 4] = to_tf32(bv1.x); Bs[buf][br][bc + 5] = to_tf32(bv1.y);
            Bs[buf][br][bc + 6] = to_tf32(bv1.z); Bs[buf][br][bc + 7] = to_tf32(bv1.w);
            __syncthreads();
        }
    }
#pragma unroll
    for (int m = 0; m < 2; m++) {
        int r = row0 + wr + (m << 4) + g;
#pragma unroll
        for (int n = 0; n < 8; n++) {
            int c = col0 + wc + (n << 3) + (tig << 1);
            *(float2*)&C[(long long)r * N + c] =
                make_float2(acc[m][n][0], acc[m][n][1]);
            *(float2*)&C[(long long)(r + 8) * N + c] =
                make_float2(acc[m][n][2], acc[m][n][3]);
        }
    }
}

// ------- 64x128x16 fp32 variant with optional row indirection --------------
__global__ __launch_bounds__(256, 2)
void sgemm64_kernel(const float* __restrict__ A, const float* __restrict__ Bm,
                    float* __restrict__ C, int M, int N, int K,
                    const int* __restrict__ ord) {
    __shared__ float As[2][16][64];
    __shared__ float Bs[2][16][128];
    const int tid  = threadIdx.x;
    const int row0 = blockIdx.y * 64, col0 = blockIdx.x * 128;
    const int ar = tid >> 2, ac = (tid & 3) << 2;
    const int br = tid >> 4, bc = (tid & 15) << 3;
    long long arow = row0 + ar;
    if (ord) {
        int r = row0 + ar;
        int b = r >> 9, slot = r & (NP - 1);
        arow = (long long)b * NT + ord[b * NT + slot];
    }
    const float* Ap = A + arow * K + ac;
    const float* Bp = Bm + (long long)br * N + col0 + bc;
    const int tx4 = (tid & 15) << 2, ty4 = (tid >> 4) << 2;

    float acc[4][8] = {};
    float af[2][4], bf[2][8];
    float4 av = *(const float4*)Ap;
    float4 bv0 = *(const float4*)Bp;
    float4 bv1 = *(const float4*)(Bp + 4);
    int buf = 0;
    As[0][ac + 0][ar] = av.x; As[0][ac + 1][ar] = av.y;
    As[0][ac + 2][ar] = av.z; As[0][ac + 3][ar] = av.w;
    *(float4*)&Bs[0][br][bc]     = bv0;
    *(float4*)&Bs[0][br][bc + 4] = bv1;
    __syncthreads();
    *(float4*)&af[0][0] = *(const float4*)&As[0][0][ty4];
    *(float4*)&bf[0][0] = *(const float4*)&Bs[0][0][tx4];
    *(float4*)&bf[0][4] = *(const float4*)&Bs[0][0][tx4 + 64];

    for (int k0 = 16; k0 <= K; k0 += 16) {
        if (k0 < K) {
            av  = *(const float4*)(Ap + k0);
            bv0 = *(const float4*)(Bp + (long long)k0 * N);
            bv1 = *(const float4*)(Bp + (long long)k0 * N + 4);
        }
#pragma unroll
        for (int kk = 0; kk < 16; kk++) {
            const int cur = kk & 1;
            if (kk < 15) {
                const int nxt = cur ^ 1;
                *(float4*)&af[nxt][0] = *(const float4*)&As[buf][kk + 1][ty4];
                *(float4*)&bf[nxt][0] = *(const float4*)&Bs[buf][kk + 1][tx4];
                *(float4*)&bf[nxt][4] = *(const float4*)&Bs[buf][kk + 1][tx4 + 64];
            }
#pragma unroll
            for (int i = 0; i < 4; i++)
#pragma unroll
                for (int j = 0; j < 8; j++)
                    acc[i][j] = fmaf(af[cur][i], bf[cur][j], acc[i][j]);
        }
        if (k0 < K) {
            buf ^= 1;
            As[buf][ac + 0][ar] = av.x; As[buf][ac + 1][ar] = av.y;
            As[buf][ac + 2][ar] = av.z; As[buf][ac + 3][ar] = av.w;
            *(float4*)&Bs[buf][br][bc]     = bv0;
            *(float4*)&Bs[buf][br][bc + 4] = bv1;
            __syncthreads();
            *(float4*)&af[0][0] = *(const float4*)&As[buf][0][ty4];
            *(float4*)&bf[0][0] = *(const float4*)&Bs[buf][0][tx4];
            *(float4*)&bf[0][4] = *(const float4*)&Bs[buf][0][tx4 + 64];
        }
    }
#pragma unroll
    for (int i = 0; i < 4; i++) {
        float* crow = C + (long long)(row0 + ty4 + i) * N + col0;
        *(float4*)(crow + tx4)      = make_float4(acc[i][0], acc[i][1], acc[i][2], acc[i][3]);
        *(float4*)(crow + tx4 + 64) = make_float4(acc[i][4], acc[i][5], acc[i][6], acc[i][7]);
    }
}

// ---------------- scores: sigmoid(relu(h) . w2); also resets flagcnt -------
__global__ void score_kernel(const float* __restrict__ w2) {
    if (blockIdx.x == 0 && threadIdx.x == 0) g_flagcnt = 0;
    int gw = (blockIdx.x * blockDim.x + threadIdx.x) >> 5;
    int lane = threadIdx.x & 31;
    if (gw >= NBT) return;
    const float* hr = g_h + (long long)gw * NH;
    float s = 0.f;
#pragma unroll
    for (int j = 0; j < NH / 32; j++) {
        int c = lane + (j << 5);
        float v = hr[c];
        v = fmaxf(v, 0.f);
        s = fmaf(v, w2[c], s);
    }
#pragma unroll
    for (int o = 16; o; o >>= 1) s += __shfl_xor_sync(0xffffffffu, s, o);
    if (lane == 0) g_scores[gw] = 1.0f / (1.0f + expf(-s));
}

// ---------------- per-batch bitonic sort ----------------
__global__ void sort_kernel() {
    __shared__ float sk[NT];
    __shared__ int   si[NT];
    int b = blockIdx.x, t = threadIdx.x;
    sk[t]        = g_scores[b * NT + t];        si[t]        = t;
    sk[t + 1024] = g_scores[b * NT + t + 1024]; si[t + 1024] = t + 1024;
    __syncthreads();
    for (int kk = 2; kk <= NT; kk <<= 1) {
        for (int j = kk >> 1; j > 0; j >>= 1) {
            for (int i = t; i < NT; i += 1024) {
                int ixj = i ^ j;
                if (ixj > i) {
                    bool ord = ((i & kk) == 0);
                    float s1 = sk[i], s2 = sk[ixj];
                    int   i1 = si[i], i2 = si[ixj];
                    bool pre = (s2 > s1) || (s2 == s1 && i2 < i1);
                    if (pre == ord) { sk[i] = s2; sk[ixj] = s1; si[i] = i2; si[ixj] = i1; }
                }
            }
            __syncthreads();
        }
    }
    g_order[b * NT + t]          = si[t];
    g_order[b * NT + t + 1024]   = si[t + 1024];
    g_sscores[b * NT + t]        = sk[t];
    g_sscores[b * NT + t + 1024] = sk[t + 1024];
}

// ---- fused at-risk flagging + compaction ----------------------------------
__global__ void flag_compact_kernel(const float* __restrict__ pri_in) {
    __shared__ float pr[NP];
    int b = blockIdx.y;
    for (int i = threadIdx.x; i < NP; i += blockDim.x) pr[i] = pri_in[b * NP + i];
    __syncthreads();
    int p = blockIdx.x * blockDim.x + threadIdx.x;
    int gi = b * NT + p;
    float s = g_sscores[gi];
    bool f = fabsf(s - 0.5f) < TAUF;
    if (p > 0)      f |= fabsf(s - g_sscores[gi - 1]) < TAUF;
    if (p < NT - 1) f |= fabsf(s - g_sscores[gi + 1]) < TAUF;
#pragma unroll 8
    for (int i = 0; i < NP; i++) f |= fabsf(s - pr[i]) < TAUF;
    if (f) {
        int pos = atomicAdd(&g_flagcnt, 1);
        g_flaglist[pos] = b * NT + g_order[gi];
    }
}

// ---- double-float helpers ----
__device__ __forceinline__ void twoProd(float a, float b, float& p, float& e) {
    p = a * b;
    e = fmaf(a, b, -p);
}
__device__ __forceinline__ void twoSum(float a, float b, float& s, float& e) {
    s = a + b;
    float bb = s - a;
    e = (a - (s - bb)) + (b - bb);
}

__global__ void recompute_kernel(const float* __restrict__ tokens,
                                 const float* __restrict__ w1,
                                 const float* __restrict__ w2) {
    __shared__ double red[256];
    int j = threadIdx.x;
    int n = g_flagcnt;
    if (blockIdx.x >= n) return;
    for (int li = blockIdx.x; li < n; li += gridDim.x) {
        int g = g_flaglist[li];
        const float* x = tokens + (long long)g * ND;
        const float* wcol = w1 + j;
        float hi = 0.f, lo = 0.f;
        for (int d = 0; d < ND; d++) {
            float p, pe, t;
            twoProd(x[d], wcol[(long long)d * NH], p, pe);
            twoSum(hi, p, hi, t);
            lo += t + pe;
        }
        double hd = (double)hi + (double)lo;
        float hf = fmaxf((float)hd, 0.0f);
        red[j] = (double)hf * (double)w2[j];
        __syncthreads();
        for (int s = 128; s; s >>= 1) {
            if (j < s) red[j] += red[j + s];
            __syncthreads();
        }
        if (j == 0) {
            double z = red[0];
            g_scores[g] = (float)(1.0 / (1.0 + exp(-z)));
        }
        __syncthreads();
    }
}

// ---------------- wide pool copy ----------------
__global__ void copy_pool_kernel(const float* __restrict__ pool_in) {
    int i = blockIdx.x * blockDim.x + threadIdx.x;
    ((float4*)g_pool)[i] = ((const float4*)pool_in)[i];
}

// ---- sequential pool update, deferred-write -------------------------------
__global__ void update_kernel(const float* __restrict__ pri_in,
                              const int* __restrict__ counts_in) {
    int b = blockIdx.x, t = threadIdx.x;
    int lane = t & 31, wid = t >> 5;
    __shared__ float pri[NP];
    __shared__ float ssl[NP];
    __shared__ int   lastw[NP];
    __shared__ float gmin[16];
    __shared__ int   gidx[16];
    __shared__ int   sh_cnt;
    pri[t]         = pri_in[b * NP + t];
    pri[t + 256]   = pri_in[b * NP + t + 256];
    ssl[t]         = g_sscores[b * NT + t];
    ssl[t + 256]   = g_sscores[b * NT + t + 256];
    lastw[t]       = -1;
    lastw[t + 256] = -1;
    __syncthreads();

    if (wid == 0) {
        for (int g = 0; g < 16; g++) {
            float v = pri[(g << 5) + lane];
            int  ix = (g << 5) + lane;
#pragma unroll
            for (int o = 16; o; o >>= 1) {
                float ov = __shfl_xor_sync(0xffffffffu, v, o);
                int   oi = __shfl_xor_sync(0xffffffffu, ix, o);
                if (ov < v || (ov == v && oi < ix)) { v = ov; ix = oi; }
            }
            if (lane == 0) { gmin[g] = v; gidx[g] = ix; }
        }
        __syncwarp();
        int cnt = counts_in[b];
        for (int slot = 0; slot < NP; slot++) {
            float sc = ssl[slot];
            if (!(sc > 0.5f)) break;
            if (cnt < NP) {
                int ins = cnt++;
                if (lane == 0) { pri[ins] = sc; lastw[ins] = slot; }
                __syncwarp();
                int g = ins >> 5;
                float v = pri[(g << 5) + lane];
                int  ix = (g << 5) + lane;
#pragma unroll
                for (int o = 16; o; o >>= 1) {
                    float ov = __shfl_xor_sync(0xffffffffu, v, o);
                    int   oi = __shfl_xor_sync(0xffffffffu, ix, o);
                    if (ov < v || (ov == v && oi < ix)) { v = ov; ix = oi; }
                }
                if (lane == 0) { gmin[g] = v; gidx[g] = ix; }
                __syncwarp();
            }
            if (cnt >= NP) {
                float v = (lane < 16) ? gmin[lane] : 3.4e38f;
                int  ix = (lane < 16) ? gidx[lane] : 0x7fffffff;
#pragma unroll
                for (int o = 8; o; o >>= 1) {
                    float ov = __shfl_xor_sync(0xffffffffu, v, o);
                    int   oi = __shfl_xor_sync(0xffffffffu, ix, o);
                    if (ov < v || (ov == v && oi < ix)) { v = ov; ix = oi; }
                }
                v  = __shfl_sync(0xffffffffu, v, 0);
                ix = __shfl_sync(0xffffffffu, ix, 0);
                if (sc > v) {
                    if (lane == 0) { pri[ix] = sc; lastw[ix] = slot; }
                    __syncwarp();
                    int g = ix >> 5;
                    float vv = pri[(g << 5) + lane];
                    int   ii = (g << 5) + lane;
#pragma unroll
                    for (int o = 16; o; o >>= 1) {
                        float ov = __shfl_xor_sync(0xffffffffu, vv, o);
                        int   oi = __shfl_xor_sync(0xffffffffu, ii, o);
                        if (ov < vv || (ov == vv && oi < ii)) { vv = ov; ii = oi; }
                    }
                    if (lane == 0) { gmin[g] = vv; gidx[g] = ii; }
                    __syncwarp();
                }
            }
        }
        if (lane == 0) sh_cnt = cnt;
    }
    __syncthreads();

    g_pri[b * NP + t]       = pri[t];
    g_pri[b * NP + t + 256] = pri[t + 256];
    if (t == 0) g_counts[b] = sh_cnt;

    float*       poolb = g_pool + (long long)b * NP * NS;
    const float* summb = g_sum + (long long)b * NP * NS;
    for (int d = wid; d < NP; d += 8) {
        int s = lastw[d];
        if (s >= 0) {
            const float4* srcr = (const float4*)(summb + (long long)s * NS);
            float4*       dstr = (float4*)(poolb + (long long)d * NS);
            dstr[lane]      = srcr[lane];
            dstr[lane + 32] = srcr[lane + 32];
        }
    }
}

// ---------------- generic batched transpose ----------------
__global__ void transpose_kernel(const float* __restrict__ src, float* __restrict__ dst,
                                 int R, int C, long long sS, long long sD) {
    __shared__ float tile[32][33];
    src += (long long)blockIdx.z * sS;
    dst += (long long)blockIdx.z * sD;
    int r0 = blockIdx.x * 32, c0 = blockIdx.y * 32;
    int x = threadIdx.x, y = threadIdx.y;
#pragma unroll
    for (int i = 0; i < 32; i += 8)
        tile[y + i][x] = src[(long long)(r0 + y + i) * C + c0 + x];
    __syncthreads();
#pragma unroll
    for (int i = 0; i < 32; i += 8)
        dst[(long long)(c0 + y + i) * R + r0 + x] = tile[x][y + i];
}

// ---------------- masked softmax ----------------
__global__ void softmax_kernel() {
    int gw = (blockIdx.x * blockDim.x + threadIdx.x) >> 5;
    int lane = threadIdx.x & 31;
    if (gw >= NBT) return;
    int b = gw >> 11;
    int cnt = g_counts[b];
    float* row = g_attn + (long long)gw * NP;
    float vals[NP / 32];
    float m = -1e30f;
#pragma unroll
    for (int j = 0; j < NP / 32; j++) {
        int p = lane + (j << 5);
        float v = row[p] * 0.0625f;
        vals[j] = v;
        if (p < cnt) m = fmaxf(m, v);
    }
#pragma unroll
    for (int o = 16; o; o >>= 1) m = fmaxf(m, __shfl_xor_sync(0xffffffffu, m, o));
    float s = 0.f;
#pragma unroll
    for (int j = 0; j < NP / 32; j++) {
        int p = lane + (j << 5);
        float e = (p < cnt) ? expf(vals[j] - m) : 0.f;
        vals[j] = e;
        s += e;
    }
#pragma unroll
    for (int o = 16; o; o >>= 1) s += __shfl_xor_sync(0xffffffffu, s, o);
    float inv = (cnt > 0) ? 1.f / s : 0.f;
#pragma unroll
    for (int j = 0; j < NP / 32; j++) row[lane + (j << 5)] = vals[j] * inv;
}

// ---------------- export ----------------
__global__ void export_kernel(float* __restrict__ dst) {
    int i = blockIdx.x * blockDim.x + threadIdx.x;
    constexpr int PS = NB * NP * NS;
    if (i < PS) dst[i] = g_pool[i];
    else if (i < PS + NB * NP) dst[i] = g_pri[i - PS];
    else if (i < PS + NB * NP + NB) dst[i] = (float)g_counts[i - PS - NB * NP];
}

// ---------------- launch ----------------
extern "C" void kernel_launch(void* const* d_in, const int* in_sizes, int n_in,
                              void* d_out, int out_size) {
    const float* tokens = (const float*)d_in[0];
    const float* pool   = (const float*)d_in[1];
    const float* pri    = (const float*)d_in[2];
    const int*   counts = (const int*)d_in[3];
    const float* w1     = (const float*)d_in[4];
    const float* w2     = (const float*)d_in[5];
    const float* w_sum  = (const float*)d_in[6];
    const float* wq     = (const float*)d_in[7];
    const float* wk     = (const float*)d_in[8];
    const float* wv     = (const float*)d_in[9];
    float* out = (float*)d_out;
    (void)in_sizes; (void)n_in;

    float *ph, *pq, *psum, *ppool, *pwkT, *pwqk, *ppoolT, *pap, *pattn;
    int* pord;
    cudaGetSymbolAddress((void**)&ph,     g_h);
    cudaGetSymbolAddress((void**)&pq,     g_q);
    cudaGetSymbolAddress((void**)&psum,   g_sum);
    cudaGetSymbolAddress((void**)&ppool,  g_pool);
    cudaGetSymbolAddress((void**)&pwkT,   g_wkT);
    cudaGetSymbolAddress((void**)&pwqk,   g_wqk);
    cudaGetSymbolAddress((void**)&ppoolT, g_poolT);
    cudaGetSymbolAddress((void**)&pap,    g_ap);
    cudaGetSymbolAddress((void**)&pattn,  g_attn);
    cudaGetSymbolAddress((void**)&pord,   g_order);

    cudaStream_t s1;
    cudaStreamCreateWithFlags(&s1, cudaStreamNonBlocking);
    cudaEvent_t evFork, evCP, evQK, evUPD, evEXP;
    cudaEventCreateWithFlags(&evFork, cudaEventDisableTiming);
    cudaEventCreateWithFlags(&evCP, cudaEventDisableTiming);
    cudaEventCreateWithFlags(&evQK, cudaEventDisableTiming);
    cudaEventCreateWithFlags(&evUPD, cudaEventDisableTiming);
    cudaEventCreateWithFlags(&evEXP, cudaEventDisableTiming);

    cudaEventRecord(evFork, 0);
    cudaStreamWaitEvent(s1, evFork, 0);
    // s1: pool copy + qk chain (wkT -> wqk fp32 -> qk tf32)
    copy_pool_kernel<<<(NB * NP * NS / 4) / 256, 256, 0, s1>>>(pool);
    cudaEventRecord(evCP, s1);
    transpose_kernel<<<dim3(NS / 32, NS / 32, 1), dim3(32, 8), 0, s1>>>(wk, pwkT, NS, NS, 0, 0);
    sgemm128_kernel<<<dim3(NS / 128, ND / 128, 1), 256, 0, s1>>>(wq, pwkT, pwqk, ND, NS, NS, NS, 0, 0, 0);
    tgemm128_kernel<<<dim3(NS / 128, NBT / 128, 1), 256, 0, s1>>>(tokens, pwqk, pq, NBT, NS, ND, ND, 0, 0, 0);
    cudaEventRecord(evQK, s1);

    // main: score path (fp32)
    sgemm128_kernel<<<dim3(NH / 128, NBT / 128, 1), 256>>>(tokens, w1, ph, NBT, NH, ND, ND, 0, 0, 0);
    score_kernel<<<NBT / 8, 256>>>(w2);
    sort_kernel<<<NB, 1024>>>();
    flag_compact_kernel<<<dim3(NT / 256, NB), 256>>>(pri);
    recompute_kernel<<<256, 256>>>(tokens, w1, w2);
    sort_kernel<<<NB, 1024>>>();
    // summaries = tokens[order[0:512]] @ w_sum (fp32, gather-free)
    sgemm64_kernel<<<dim3(NS / 128, NB * NP / 64, 1), 256>>>(tokens, w_sum, psum, NB * NP, NS, ND, pord);
    cudaStreamWaitEvent(0, evCP, 0);
    update_kernel<<<NB, 256>>>(pri, counts);
    cudaEventRecord(evUPD, 0);
    constexpr int RET = NBT * ND;
    constexpr int REST = NB * NP * NS + NB * NP + NB;
    if (out_size >= RET + REST) {
        cudaStreamWaitEvent(s1, evUPD, 0);
        export_kernel<<<(REST + 255) / 256, 256, 0, s1>>>(out + (long long)RET);
    }
    transpose_kernel<<<dim3(NP / 32, NS / 32, NB), dim3(32, 8)>>>(ppool, ppoolT, NP, NS,
        (long long)NP * NS, (long long)NS * NP);
    cudaStreamWaitEvent(0, evQK, 0);
    // attn = qk @ poolT (tf32)
    tgemm128_kernel<<<dim3(NP / 128, NT / 128, NB), 256>>>(pq, ppoolT, pattn, NT, NP, NS, NS,
        (long long)NT * NS, (long long)NS * NP, (long long)NT * NP);
    softmax_kernel<<<NBT / 8, 256>>>();
    // ap = attn @ pool (tf32) ; retrieved = ap @ wv (tf32)
    tgemm128_kernel<<<dim3(NS / 128, NT / 128, NB), 256>>>(pattn, ppool, pap, NT, NS, NP, NP,
        (long long)NT * NP, (long long)NP * NS, (long long)NT * NS);
    tgemm128_kernel<<<dim3(ND / 128, NBT / 128, 1), 256>>>(pap, wv, out, NBT, ND, NS, NS, 0, 0, 0);
    cudaEventRecord(evEXP, s1);
    cudaStreamWaitEvent(0, evEXP, 0);
}